// round 11
// baseline (speedup 1.0000x reference)
#include <cuda_runtime.h>
#include <cuda_bf16.h>
#include <cuda_fp16.h>
#include <cstdint>

// ----------------------------------------------------------------------------
// SelfAttention (SAGAN-style), B=4, C=256, N=4096.
// Energy: bf16 split-GEMM (hi/lo, K x3) via mma.sync (logit abs-error needs it).
// A*V:    single-stream fp16 mma.sync (independent quantization errors on P,V
//         give norm-relative error ~4e-4 regardless of attention concentration).
// ----------------------------------------------------------------------------

#define BB   4
#define CC   256
#define NT   4096

// ---------------- scratch (__device__ globals; no allocation) ---------------
__device__ __nv_bfloat16 g_Qs[(size_t)BB * NT * 512];      // [b][n][hi 256 | lo 256]
__device__ __nv_bfloat16 g_Ks[(size_t)BB * NT * 512];      // [b][m][hi 256 | lo 256]
__device__ __half        g_Vh[(size_t)BB * CC * NT];       // [b][o][m]  V^T fp16
__device__ __half        g_Ph[(size_t)BB * NT * NT];       // [b][n][m]  attention fp16
__device__ float         g_E [(size_t)BB * NT * NT];       // energy fp32

// ---------------- helpers ----------------------------------------------------
__device__ __forceinline__ uint32_t smem_u32(const void* p) {
    uint32_t a;
    asm("{ .reg .u64 t; cvta.to.shared.u64 t, %1; cvt.u32.u64 %0, t; }"
        : "=r"(a) : "l"(p));
    return a;
}
__device__ __forceinline__ void cp_async16(uint32_t dst, const void* src) {
    asm volatile("cp.async.cg.shared.global [%0], [%1], 16;" :: "r"(dst), "l"(src));
}
__device__ __forceinline__ void cp_commit() {
    asm volatile("cp.async.commit_group;" ::: "memory");
}
template <int N>
__device__ __forceinline__ void cp_wait() {
    asm volatile("cp.async.wait_group %0;" :: "n"(N) : "memory");
}
__device__ __forceinline__ void ldm_x4(uint32_t& r0, uint32_t& r1,
                                       uint32_t& r2, uint32_t& r3, uint32_t addr) {
    asm volatile("ldmatrix.sync.aligned.m8n8.x4.shared.b16 {%0,%1,%2,%3}, [%4];"
        : "=r"(r0), "=r"(r1), "=r"(r2), "=r"(r3) : "r"(addr));
}
template <bool IS_BF16>
__device__ __forceinline__ void mma16816(float* d, const uint32_t* a, const uint32_t* b) {
    if (IS_BF16)
        asm volatile(
            "mma.sync.aligned.m16n8k16.row.col.f32.bf16.bf16.f32 "
            "{%0,%1,%2,%3}, {%4,%5,%6,%7}, {%8,%9}, {%0,%1,%2,%3};"
            : "+f"(d[0]), "+f"(d[1]), "+f"(d[2]), "+f"(d[3])
            : "r"(a[0]), "r"(a[1]), "r"(a[2]), "r"(a[3]), "r"(b[0]), "r"(b[1]));
    else
        asm volatile(
            "mma.sync.aligned.m16n8k16.row.col.f32.f16.f16.f32 "
            "{%0,%1,%2,%3}, {%4,%5,%6,%7}, {%8,%9}, {%0,%1,%2,%3};"
            : "+f"(d[0]), "+f"(d[1]), "+f"(d[2]), "+f"(d[3])
            : "r"(a[0]), "r"(a[1]), "r"(a[2]), "r"(a[3]), "r"(b[0]), "r"(b[1]));
}
#define SWZ(o) ((o) ^ (((o) >> 3) & 0x70))

__device__ __forceinline__ void split_bf16(float v, __nv_bfloat16& h, __nv_bfloat16& l) {
    h = __float2bfloat16(v);
    l = __float2bfloat16(v - __bfloat162float(h));
}

// ---------------- GEMM mainloop config --------------------------------------
#define STAGES      3
#define CHUNK       64                 // b16 K elems per chunk (128B rows, SW128)
#define TILE_BYTES  16384              // 128 rows * 128B
#define STAGE_BYTES (2 * TILE_BYTES)
#define SM_GEMM     (STAGES * STAGE_BYTES)     // 96KB
#define SM_TS       (128 * 132 * 4)            // 67.6KB transpose scratch (AV)
#define SM_TOTAL    (SM_GEMM > SM_TS ? SM_GEMM : SM_TS)

// C[128 x 128] += A[row][k] * B[row][k] (both K-contiguous, b16 elements).
// NS=3: streams A={hi,hi,lo}, B={hi,lo,hi} (split-bf16 K-extension).
// NS=1: plain single-precision-operand GEMM (fp16).
// Chunk c lives in buffer (c % STAGES); c+2 prefetched into ((c+2) % STAGES).
template <int NS, bool IS_BF16>
__device__ __forceinline__ void gemm_mainloop(
    char* smem, float acc[2][8][4],
    const uint16_t* __restrict__ aBase, int aStride, int loA,
    const uint16_t* __restrict__ bBase, int bStride, int loB, int nsc)
{
    const int tid  = threadIdx.x;
    const int wid  = tid >> 5, lane = tid & 31;
    const int wm   = wid >> 1, wn = wid & 1;
    const int nch  = NS * nsc;
    const uint32_t sb = smem_u32(smem);

    // static ldmatrix address components
    const int arow  = wm * 32 + (lane & 15);
    const int acolb = (lane >> 4) * 16;
    const int brow  = wn * 64 + ((lane >> 4) << 3) + (lane & 7);
    const int bcolb = ((lane >> 3) & 1) * 16;

#define LOAD_CHUNK(c, stg) do {                                                  \
        int _st = (c) / nsc;                                                     \
        int _kf = ((c) % nsc) * CHUNK;                                           \
        int _ao = ((NS == 3 && _st == 2) ? loA : 0) + _kf;                       \
        int _bo = ((NS == 3 && _st == 1) ? loB : 0) + _kf;                       \
        uint32_t _ab = sb + (stg) * STAGE_BYTES;                                 \
        uint32_t _bb = _ab + TILE_BYTES;                                         \
        _Pragma("unroll")                                                        \
        for (int _p = 0; _p < 4; _p++) {                                         \
            int _idx = tid + _p * 256;                                           \
            int _row = _idx >> 3, _ch = _idx & 7;                                \
            uint32_t _so = SWZ(_row * 128 + _ch * 16);                           \
            cp_async16(_ab + _so, aBase + (size_t)_row * aStride + _ao + _ch * 8); \
            cp_async16(_bb + _so, bBase + (size_t)_row * bStride + _bo + _ch * 8); \
        }                                                                        \
        cp_commit();                                                             \
    } while (0)

#pragma unroll
    for (int s = 0; s < STAGES - 1; s++) LOAD_CHUNK(s, s);

    int cur = 0, nxt = STAGES - 1;
    for (int c = 0; c < nch; c++) {
        // Last iteration has only its own group outstanding: must wait fully.
        if (c < nch - 1) cp_wait<STAGES - 2>();
        else             cp_wait<0>();
        __syncthreads();
        const uint32_t abase = sb + cur * STAGE_BYTES;
        const uint32_t bbase = abase + TILE_BYTES;
#pragma unroll
        for (int ki = 0; ki < 4; ki++) {
            uint32_t af[2][4], bf[4][4];
#pragma unroll
            for (int mi = 0; mi < 2; mi++)
                ldm_x4(af[mi][0], af[mi][1], af[mi][2], af[mi][3],
                       abase + SWZ((arow + mi * 16) * 128 + ki * 32 + acolb));
#pragma unroll
            for (int nj = 0; nj < 4; nj++)
                ldm_x4(bf[nj][0], bf[nj][1], bf[nj][2], bf[nj][3],
                       bbase + SWZ((brow + nj * 16) * 128 + ki * 32 + bcolb));
#pragma unroll
            for (int mi = 0; mi < 2; mi++)
#pragma unroll
                for (int nj = 0; nj < 4; nj++) {
                    mma16816<IS_BF16>(acc[mi][nj * 2 + 0], af[mi], &bf[nj][0]);
                    mma16816<IS_BF16>(acc[mi][nj * 2 + 1], af[mi], &bf[nj][2]);
                }
        }
        if (c + STAGES - 1 < nch) LOAD_CHUNK(c + STAGES - 1, nxt);
        cur = (cur + 1 == STAGES) ? 0 : cur + 1;
        nxt = (nxt + 1 == STAGES) ? 0 : nxt + 1;
    }
#undef LOAD_CHUNK
}

// ============================================================================
// Kernel 1: projections (fp32 SIMT) -> Q/K split bf16, V^T plain fp16.
// grid (NT/128, CC/128, B*3), block 256
// ============================================================================
__global__ __launch_bounds__(256, 2)
void proj_kernel(const float* __restrict__ x,
                 const float* __restrict__ Wq, const float* __restrict__ bq,
                 const float* __restrict__ Wk, const float* __restrict__ bk,
                 const float* __restrict__ Wv, const float* __restrict__ bv)
{
    __shared__ float As[16][132];
    __shared__ float Bs[16][132];

    const int z = blockIdx.z;
    const int b = z / 3, p = z % 3;
    const float* W    = (p == 0) ? Wq : (p == 1) ? Wk : Wv;
    const float* bias = (p == 0) ? bq : (p == 1) ? bk : bv;

    const int n0 = blockIdx.x * 128;
    const int o0 = blockIdx.y * 128;
    const float* xb = x + (size_t)b * CC * NT;

    const int tid = threadIdx.x;
    const int tx = tid & 15, ty = tid >> 4;

    float acc[8][8];
#pragma unroll
    for (int i = 0; i < 8; i++)
#pragma unroll
        for (int j = 0; j < 8; j++) acc[i][j] = 0.f;

    const int la_k = tid >> 5;
    const int la_n = (tid & 31) * 4;
    const int lb_r = tid >> 2;
    const int lb_c = (tid & 3) * 4;

    for (int c0 = 0; c0 < CC; c0 += 16) {
#pragma unroll
        for (int it = 0; it < 2; it++) {
            int k = la_k + it * 8;
            float4 v = *(const float4*)&xb[(size_t)(c0 + k) * NT + n0 + la_n];
            *(float4*)&As[k][la_n] = v;
        }
#pragma unroll
        for (int it = 0; it < 2; it++) {
            int r = lb_r + it * 64;
            float4 v = *(const float4*)&W[(size_t)(o0 + r) * CC + c0 + lb_c];
            Bs[lb_c + 0][r] = v.x; Bs[lb_c + 1][r] = v.y;
            Bs[lb_c + 2][r] = v.z; Bs[lb_c + 3][r] = v.w;
        }
        __syncthreads();
#pragma unroll
        for (int kc = 0; kc < 16; kc++) {
            float a[8], bb2[8];
            *(float4*)&a[0]   = *(float4*)&As[kc][ty * 8];
            *(float4*)&a[4]   = *(float4*)&As[kc][ty * 8 + 4];
            *(float4*)&bb2[0] = *(float4*)&Bs[kc][tx * 8];
            *(float4*)&bb2[4] = *(float4*)&Bs[kc][tx * 8 + 4];
#pragma unroll
            for (int i = 0; i < 8; i++)
#pragma unroll
                for (int j = 0; j < 8; j++) acc[i][j] += a[i] * bb2[j];
        }
        __syncthreads();
    }

    float br[8];
#pragma unroll
    for (int j = 0; j < 8; j++) br[j] = bias[o0 + tx * 8 + j];

    if (p < 2) {
        __nv_bfloat16* Out = (p == 0) ? g_Qs : g_Ks;
#pragma unroll
        for (int i = 0; i < 8; i++) {
            __nv_bfloat16 h8[8], l8[8];
#pragma unroll
            for (int j = 0; j < 8; j++) split_bf16(acc[i][j] + br[j], h8[j], l8[j]);
            __nv_bfloat16* dst = Out + ((size_t)(b * NT + n0 + ty * 8 + i)) * 512 + o0 + tx * 8;
            *(uint4*)dst         = *(uint4*)h8;
            *(uint4*)(dst + 256) = *(uint4*)l8;
        }
    } else {
        // V transposed, plain fp16: g_Vh[b][o][m]
#pragma unroll
        for (int j = 0; j < 8; j++) {
            __half h8[8];
#pragma unroll
            for (int i = 0; i < 8; i++) h8[i] = __float2half_rn(acc[i][j] + br[j]);
            __half* dst = g_Vh + ((size_t)(b * CC + o0 + tx * 8 + j)) * NT + n0 + ty * 8;
            *(uint4*)dst = *(uint4*)h8;
        }
    }
}

// ============================================================================
// Kernel 2: energy E[b][n][m], split-bf16 3-stream.  grid (32 m, 32 n, B), 256
// ============================================================================
__global__ __launch_bounds__(256)
void energy_mma_kernel()
{
    extern __shared__ char smem[];
    const int b = blockIdx.z, m0 = blockIdx.x * 128, n0 = blockIdx.y * 128;
    const int wid = threadIdx.x >> 5, lane = threadIdx.x & 31;
    const int wm = wid >> 1, wn = wid & 1;

    float acc[2][8][4];
#pragma unroll
    for (int mi = 0; mi < 2; mi++)
#pragma unroll
        for (int j = 0; j < 8; j++)
#pragma unroll
            for (int k = 0; k < 4; k++) acc[mi][j][k] = 0.f;

    gemm_mainloop<3, true>(smem, acc,
                  (const uint16_t*)(g_Qs + (size_t)(b * NT + n0) * 512), 512, 256,
                  (const uint16_t*)(g_Ks + (size_t)(b * NT + m0) * 512), 512, 256, 4);

    float* Eb = g_E + (size_t)b * NT * NT;
#pragma unroll
    for (int mi = 0; mi < 2; mi++) {
        int r = n0 + wm * 32 + mi * 16 + (lane >> 2);
#pragma unroll
        for (int j = 0; j < 8; j++) {
            int cm = m0 + wn * 64 + j * 8 + (lane & 3) * 2;
            *(float2*)&Eb[(size_t)r * NT + cm]       = make_float2(acc[mi][j][0], acc[mi][j][1]);
            *(float2*)&Eb[(size_t)(r + 8) * NT + cm] = make_float2(acc[mi][j][2], acc[mi][j][3]);
        }
    }
}

// ============================================================================
// Kernel 3: row softmax fp32 -> plain fp16 attention.  grid (B*NT), block 256
// ============================================================================
__device__ __forceinline__ float warpMax(float v) {
#pragma unroll
    for (int o = 16; o > 0; o >>= 1) v = fmaxf(v, __shfl_xor_sync(0xffffffffu, v, o));
    return v;
}
__device__ __forceinline__ float warpSum(float v) {
#pragma unroll
    for (int o = 16; o > 0; o >>= 1) v += __shfl_xor_sync(0xffffffffu, v, o);
    return v;
}

__global__ __launch_bounds__(256)
void softmax_kernel()
{
    __shared__ float sred[8];
    const size_t row = blockIdx.x;
    const int tid = threadIdx.x;
    const int lane = tid & 31, wid = tid >> 5;

    float v[16];
#pragma unroll
    for (int i = 0; i < 4; i++) {
        float4 t = *(const float4*)&g_E[row * NT + tid * 4 + i * 1024];
        v[i * 4 + 0] = t.x; v[i * 4 + 1] = t.y; v[i * 4 + 2] = t.z; v[i * 4 + 3] = t.w;
    }

    float mx = -3.4e38f;
#pragma unroll
    for (int i = 0; i < 16; i++) mx = fmaxf(mx, v[i]);
    mx = warpMax(mx);
    if (lane == 0) sred[wid] = mx;
    __syncthreads();
    if (wid == 0) {
        float t = (lane < 8) ? sred[lane] : -3.4e38f;
        t = warpMax(t);
        if (lane == 0) sred[0] = t;
    }
    __syncthreads();
    mx = sred[0];
    __syncthreads();

    float s = 0.f;
#pragma unroll
    for (int i = 0; i < 16; i++) { v[i] = __expf(v[i] - mx); s += v[i]; }
    s = warpSum(s);
    if (lane == 0) sred[wid] = s;
    __syncthreads();
    if (wid == 0) {
        float t = (lane < 8) ? sred[lane] : 0.f;
        t = warpSum(t);
        if (lane == 0) sred[0] = t;
    }
    __syncthreads();
    const float inv = 1.0f / sred[0];

    __half* arow = g_Ph + row * NT;
#pragma unroll
    for (int i = 0; i < 4; i++) {
        __half h4[4];
#pragma unroll
        for (int k = 0; k < 4; k++) h4[k] = __float2half_rn(v[i * 4 + k] * inv);
        *(uint2*)(arow + tid * 4 + i * 1024) = *(uint2*)h4;
    }
}

// ============================================================================
// Kernel 4: out[b][o][n] = sum_m P[n][m] V[m][o], single-stream fp16.
// grid (2 o, 32 n, B), block 256
// ============================================================================
__global__ __launch_bounds__(256)
void av_mma_kernel(float* __restrict__ out)
{
    extern __shared__ char smem[];
    const int b = blockIdx.z, o0 = blockIdx.x * 128, n0 = blockIdx.y * 128;
    const int tid = threadIdx.x;
    const int wid = tid >> 5, lane = tid & 31;
    const int wm = wid >> 1, wn = wid & 1;

    float acc[2][8][4];
#pragma unroll
    for (int mi = 0; mi < 2; mi++)
#pragma unroll
        for (int j = 0; j < 8; j++)
#pragma unroll
            for (int k = 0; k < 4; k++) acc[mi][j][k] = 0.f;

    gemm_mainloop<1, false>(smem, acc,
                  (const uint16_t*)(g_Ph + (size_t)(b * NT + n0) * NT), NT, 0,
                  (const uint16_t*)(g_Vh + (size_t)(b * CC + o0) * NT), NT, 0, 64);

    // transpose C[n][o] -> out[b][o][n] via smem (reuse pipeline buffers)
    float* ts = (float*)smem;                  // [128 n][132]
    __syncthreads();
#pragma unroll
    for (int mi = 0; mi < 2; mi++) {
        int r = wm * 32 + mi * 16 + (lane >> 2);
#pragma unroll
        for (int j = 0; j < 8; j++) {
            int o = wn * 64 + j * 8 + (lane & 3) * 2;
            *(float2*)&ts[(size_t)r * 132 + o]       = make_float2(acc[mi][j][0], acc[mi][j][1]);
            *(float2*)&ts[(size_t)(r + 8) * 132 + o] = make_float2(acc[mi][j][2], acc[mi][j][3]);
        }
    }
    __syncthreads();

    const int o = tid >> 1;
    const int nh = (tid & 1) * 64;
    float* dst = out + ((size_t)(b * CC + o0 + o)) * NT + n0 + nh;
#pragma unroll
    for (int g = 0; g < 16; g++) {
        int n = nh + g * 4;
        float4 v = make_float4(ts[(n + 0) * 132 + o], ts[(n + 1) * 132 + o],
                               ts[(n + 2) * 132 + o], ts[(n + 3) * 132 + o]);
        *(float4*)(dst + g * 4) = v;
    }
}

// ============================================================================
extern "C" void kernel_launch(void* const* d_in, const int* in_sizes, int n_in,
                              void* d_out, int out_size)
{
    const float* x  = (const float*)d_in[0];
    const float* Wq = (const float*)d_in[1];
    const float* bq = (const float*)d_in[2];
    const float* Wk = (const float*)d_in[3];
    const float* bk = (const float*)d_in[4];
    const float* Wv = (const float*)d_in[5];
    const float* bv = (const float*)d_in[6];
    float* out = (float*)d_out;

    cudaFuncSetAttribute(energy_mma_kernel,
                         cudaFuncAttributeMaxDynamicSharedMemorySize, SM_TOTAL);
    cudaFuncSetAttribute(av_mma_kernel,
                         cudaFuncAttributeMaxDynamicSharedMemorySize, SM_TOTAL);

    dim3 gproj(NT / 128, CC / 128, BB * 3);
    proj_kernel<<<gproj, 256>>>(x, Wq, bq, Wk, bk, Wv, bv);

    dim3 gen(NT / 128, NT / 128, BB);          // 32 x 32 x 4
    energy_mma_kernel<<<gen, 256, SM_TOTAL>>>();

    softmax_kernel<<<BB * NT, 256>>>();

    dim3 gav(CC / 128, NT / 128, BB);          // 2 x 32 x 4
    av_mma_kernel<<<gav, 256, SM_TOTAL>>>(out);
}

// round 16
// speedup vs baseline: 1.4115x; 1.4115x over previous
#include <cuda_runtime.h>
#include <cuda_bf16.h>
#include <cuda_fp16.h>
#include <cstdint>

// ----------------------------------------------------------------------------
// SelfAttention (SAGAN-style), B=4, C=256, N=4096.
// Energy: bf16 split-GEMM (hi/lo, K x3) -> fused exp epilogue writing fp16
//         P'' = exp(S - rowmax)*2^15 directly (no fp32 E array), rowsum via
//         atomicAdd. Rowmax from a cheap single-stream bf16 max-pass.
// A*V:    single-stream fp16 mma.sync; epilogue divides by rowsum.
// ----------------------------------------------------------------------------

#define BB   4
#define CC   256
#define NT   4096

// ---------------- scratch (__device__ globals; no allocation) ---------------
__device__ __nv_bfloat16 g_Qs[(size_t)BB * NT * 512];      // [b][n][hi 256 | lo 256]
__device__ __nv_bfloat16 g_Ks[(size_t)BB * NT * 512];      // [b][m][hi 256 | lo 256]
__device__ __half        g_Vh[(size_t)BB * CC * NT];       // [b][o][m]  V^T fp16
__device__ __half        g_Ph[(size_t)BB * NT * NT];       // [b][n][m]  P'' fp16
__device__ float         g_sum [(size_t)BB * NT];          // rowsum of P''
__device__ unsigned      g_rmax[(size_t)BB * NT];          // rowmax, order-enc

// ---------------- helpers ----------------------------------------------------
__device__ __forceinline__ uint32_t smem_u32(const void* p) {
    uint32_t a;
    asm("{ .reg .u64 t; cvta.to.shared.u64 t, %1; cvt.u32.u64 %0, t; }"
        : "=r"(a) : "l"(p));
    return a;
}
__device__ __forceinline__ void cp_async16(uint32_t dst, const void* src) {
    asm volatile("cp.async.cg.shared.global [%0], [%1], 16;" :: "r"(dst), "l"(src));
}
__device__ __forceinline__ void cp_commit() {
    asm volatile("cp.async.commit_group;" ::: "memory");
}
template <int N>
__device__ __forceinline__ void cp_wait() {
    asm volatile("cp.async.wait_group %0;" :: "n"(N) : "memory");
}
__device__ __forceinline__ void ldm_x4(uint32_t& r0, uint32_t& r1,
                                       uint32_t& r2, uint32_t& r3, uint32_t addr) {
    asm volatile("ldmatrix.sync.aligned.m8n8.x4.shared.b16 {%0,%1,%2,%3}, [%4];"
        : "=r"(r0), "=r"(r1), "=r"(r2), "=r"(r3) : "r"(addr));
}
template <bool IS_BF16>
__device__ __forceinline__ void mma16816(float* d, const uint32_t* a, const uint32_t* b) {
    if (IS_BF16)
        asm volatile(
            "mma.sync.aligned.m16n8k16.row.col.f32.bf16.bf16.f32 "
            "{%0,%1,%2,%3}, {%4,%5,%6,%7}, {%8,%9}, {%0,%1,%2,%3};"
            : "+f"(d[0]), "+f"(d[1]), "+f"(d[2]), "+f"(d[3])
            : "r"(a[0]), "r"(a[1]), "r"(a[2]), "r"(a[3]), "r"(b[0]), "r"(b[1]));
    else
        asm volatile(
            "mma.sync.aligned.m16n8k16.row.col.f32.f16.f16.f32 "
            "{%0,%1,%2,%3}, {%4,%5,%6,%7}, {%8,%9}, {%0,%1,%2,%3};"
            : "+f"(d[0]), "+f"(d[1]), "+f"(d[2]), "+f"(d[3])
            : "r"(a[0]), "r"(a[1]), "r"(a[2]), "r"(a[3]), "r"(b[0]), "r"(b[1]));
}
#define SWZ(o) ((o) ^ (((o) >> 3) & 0x70))

__device__ __forceinline__ void split_bf16(float v, __nv_bfloat16& h, __nv_bfloat16& l) {
    h = __float2bfloat16(v);
    l = __float2bfloat16(v - __bfloat162float(h));
}
// order-preserving float <-> unsigned encoding (for atomicMax on floats)
__device__ __forceinline__ unsigned fenc(float f) {
    unsigned u = __float_as_uint(f);
    return (u & 0x80000000u) ? ~u : (u | 0x80000000u);
}
__device__ __forceinline__ float fdec(unsigned u) {
    u = (u & 0x80000000u) ? (u & 0x7fffffffu) : ~u;
    return __uint_as_float(u);
}
#define ENC_NEG_INF 0x007fffffu    // fenc(-inf)

// ---------------- GEMM mainloop config --------------------------------------
#define STAGES      3
#define CHUNK       64                 // b16 K elems per chunk (128B rows, SW128)
#define TILE_BYTES  16384              // 128 rows * 128B
#define STAGE_BYTES (2 * TILE_BYTES)
#define SM_GEMM     (STAGES * STAGE_BYTES)     // 96KB
#define SM_TS       (128 * 132 * 4 + 512)      // transpose scratch + sinv (AV)
#define SM_TOTAL    (SM_GEMM > SM_TS ? SM_GEMM : SM_TS)

// C[128 x 128] += A[row][k] * B[row][k] (both K-contiguous, b16 elements).
// NS=3: streams A={hi,hi,lo}, B={hi,lo,hi} (split-bf16 K-extension).
// NS=1: plain single-operand GEMM.
// Chunk c lives in buffer (c % STAGES); c+2 prefetched into ((c+2) % STAGES).
template <int NS, bool IS_BF16>
__device__ __forceinline__ void gemm_mainloop(
    char* smem, float acc[2][8][4],
    const uint16_t* __restrict__ aBase, int aStride, int loA,
    const uint16_t* __restrict__ bBase, int bStride, int loB, int nsc)
{
    const int tid  = threadIdx.x;
    const int wid  = tid >> 5, lane = tid & 31;
    const int wm   = wid >> 1, wn = wid & 1;
    const int nch  = NS * nsc;
    const uint32_t sb = smem_u32(smem);

    const int arow  = wm * 32 + (lane & 15);
    const int acolb = (lane >> 4) * 16;
    const int brow  = wn * 64 + ((lane >> 4) << 3) + (lane & 7);
    const int bcolb = ((lane >> 3) & 1) * 16;

#define LOAD_CHUNK(c, stg) do {                                                  \
        int _st = (c) / nsc;                                                     \
        int _kf = ((c) % nsc) * CHUNK;                                           \
        int _ao = ((NS == 3 && _st == 2) ? loA : 0) + _kf;                       \
        int _bo = ((NS == 3 && _st == 1) ? loB : 0) + _kf;                       \
        uint32_t _ab = sb + (stg) * STAGE_BYTES;                                 \
        uint32_t _bb = _ab + TILE_BYTES;                                         \
        _Pragma("unroll")                                                        \
        for (int _p = 0; _p < 4; _p++) {                                         \
            int _idx = tid + _p * 256;                                           \
            int _row = _idx >> 3, _ch = _idx & 7;                                \
            uint32_t _so = SWZ(_row * 128 + _ch * 16);                           \
            cp_async16(_ab + _so, aBase + (size_t)_row * aStride + _ao + _ch * 8); \
            cp_async16(_bb + _so, bBase + (size_t)_row * bStride + _bo + _ch * 8); \
        }                                                                        \
        cp_commit();                                                             \
    } while (0)

#pragma unroll
    for (int s = 0; s < STAGES - 1; s++) LOAD_CHUNK(s, s);

    int cur = 0, nxt = STAGES - 1;
    for (int c = 0; c < nch; c++) {
        if (c < nch - 1) cp_wait<STAGES - 2>();
        else             cp_wait<0>();
        __syncthreads();
        const uint32_t abase = sb + cur * STAGE_BYTES;
        const uint32_t bbase = abase + TILE_BYTES;
#pragma unroll
        for (int ki = 0; ki < 4; ki++) {
            uint32_t af[2][4], bf[4][4];
#pragma unroll
            for (int mi = 0; mi < 2; mi++)
                ldm_x4(af[mi][0], af[mi][1], af[mi][2], af[mi][3],
                       abase + SWZ((arow + mi * 16) * 128 + ki * 32 + acolb));
#pragma unroll
            for (int nj = 0; nj < 4; nj++)
                ldm_x4(bf[nj][0], bf[nj][1], bf[nj][2], bf[nj][3],
                       bbase + SWZ((brow + nj * 16) * 128 + ki * 32 + bcolb));
#pragma unroll
            for (int mi = 0; mi < 2; mi++)
#pragma unroll
                for (int nj = 0; nj < 4; nj++) {
                    mma16816<IS_BF16>(acc[mi][nj * 2 + 0], af[mi], &bf[nj][0]);
                    mma16816<IS_BF16>(acc[mi][nj * 2 + 1], af[mi], &bf[nj][2]);
                }
        }
        if (c + STAGES - 1 < nch) LOAD_CHUNK(c + STAGES - 1, nxt);
        cur = (cur + 1 == STAGES) ? 0 : cur + 1;
        nxt = (nxt + 1 == STAGES) ? 0 : nxt + 1;
    }
#undef LOAD_CHUNK
}

// ============================================================================
// Kernel 0: zero the accumulation arrays (required per graph replay).
// ============================================================================
__global__ void zero_kernel()
{
    int i = blockIdx.x * 256 + threadIdx.x;
    if (i < BB * NT) { g_sum[i] = 0.f; g_rmax[i] = ENC_NEG_INF; }
}

// ============================================================================
// Kernel 1: projections (fp32 SIMT) -> Q/K split bf16, V^T plain fp16.
// grid (NT/128, CC/128, B*3), block 256
// ============================================================================
__global__ __launch_bounds__(256, 2)
void proj_kernel(const float* __restrict__ x,
                 const float* __restrict__ Wq, const float* __restrict__ bq,
                 const float* __restrict__ Wk, const float* __restrict__ bk,
                 const float* __restrict__ Wv, const float* __restrict__ bv)
{
    __shared__ float As[16][132];
    __shared__ float Bs[16][132];

    const int z = blockIdx.z;
    const int b = z / 3, p = z % 3;
    const float* W    = (p == 0) ? Wq : (p == 1) ? Wk : Wv;
    const float* bias = (p == 0) ? bq : (p == 1) ? bk : bv;

    const int n0 = blockIdx.x * 128;
    const int o0 = blockIdx.y * 128;
    const float* xb = x + (size_t)b * CC * NT;

    const int tid = threadIdx.x;
    const int tx = tid & 15, ty = tid >> 4;

    float acc[8][8];
#pragma unroll
    for (int i = 0; i < 8; i++)
#pragma unroll
        for (int j = 0; j < 8; j++) acc[i][j] = 0.f;

    const int la_k = tid >> 5;
    const int la_n = (tid & 31) * 4;
    const int lb_r = tid >> 2;
    const int lb_c = (tid & 3) * 4;

    for (int c0 = 0; c0 < CC; c0 += 16) {
#pragma unroll
        for (int it = 0; it < 2; it++) {
            int k = la_k + it * 8;
            float4 v = *(const float4*)&xb[(size_t)(c0 + k) * NT + n0 + la_n];
            *(float4*)&As[k][la_n] = v;
        }
#pragma unroll
        for (int it = 0; it < 2; it++) {
            int r = lb_r + it * 64;
            float4 v = *(const float4*)&W[(size_t)(o0 + r) * CC + c0 + lb_c];
            Bs[lb_c + 0][r] = v.x; Bs[lb_c + 1][r] = v.y;
            Bs[lb_c + 2][r] = v.z; Bs[lb_c + 3][r] = v.w;
        }
        __syncthreads();
#pragma unroll
        for (int kc = 0; kc < 16; kc++) {
            float a[8], bb2[8];
            *(float4*)&a[0]   = *(float4*)&As[kc][ty * 8];
            *(float4*)&a[4]   = *(float4*)&As[kc][ty * 8 + 4];
            *(float4*)&bb2[0] = *(float4*)&Bs[kc][tx * 8];
            *(float4*)&bb2[4] = *(float4*)&Bs[kc][tx * 8 + 4];
#pragma unroll
            for (int i = 0; i < 8; i++)
#pragma unroll
                for (int j = 0; j < 8; j++) acc[i][j] += a[i] * bb2[j];
        }
        __syncthreads();
    }

    float br[8];
#pragma unroll
    for (int j = 0; j < 8; j++) br[j] = bias[o0 + tx * 8 + j];

    if (p < 2) {
        __nv_bfloat16* Out = (p == 0) ? g_Qs : g_Ks;
#pragma unroll
        for (int i = 0; i < 8; i++) {
            __nv_bfloat16 h8[8], l8[8];
#pragma unroll
            for (int j = 0; j < 8; j++) split_bf16(acc[i][j] + br[j], h8[j], l8[j]);
            __nv_bfloat16* dst = Out + ((size_t)(b * NT + n0 + ty * 8 + i)) * 512 + o0 + tx * 8;
            *(uint4*)dst         = *(uint4*)h8;
            *(uint4*)(dst + 256) = *(uint4*)l8;
        }
    } else {
#pragma unroll
        for (int j = 0; j < 8; j++) {
            __half h8[8];
#pragma unroll
            for (int i = 0; i < 8; i++) h8[i] = __float2half_rn(acc[i][j] + br[j]);
            __half* dst = g_Vh + ((size_t)(b * CC + o0 + tx * 8 + j)) * NT + n0 + ty * 8;
            *(uint4*)dst = *(uint4*)h8;
        }
    }
}

// ============================================================================
// Kernel 2: maxpass — approximate rowmax of S via single-stream bf16 (hi only).
// grid (32 m, 32 n, B), block 256
// ============================================================================
__global__ __launch_bounds__(256)
void maxpass_kernel()
{
    extern __shared__ char smem[];
    const int b = blockIdx.z, m0 = blockIdx.x * 128, n0 = blockIdx.y * 128;
    const int tid = threadIdx.x;
    const int wid = tid >> 5, lane = tid & 31;
    const int wm = wid >> 1, wn = wid & 1;
    (void)m0;

    float acc[2][8][4];
#pragma unroll
    for (int mi = 0; mi < 2; mi++)
#pragma unroll
        for (int j = 0; j < 8; j++)
#pragma unroll
            for (int k = 0; k < 4; k++) acc[mi][j][k] = 0.f;

    gemm_mainloop<1, true>(smem, acc,
                  (const uint16_t*)(g_Qs + (size_t)(b * NT + n0) * 512), 512, 0,
                  (const uint16_t*)(g_Ks + (size_t)(b * NT + m0) * 512), 512, 0, 4);

    // per-lane tile rowmax: mx[mi][half]
    float mx[2][2];
#pragma unroll
    for (int mi = 0; mi < 2; mi++) {
        mx[mi][0] = -3.4e38f; mx[mi][1] = -3.4e38f;
#pragma unroll
        for (int j = 0; j < 8; j++) {
            mx[mi][0] = fmaxf(mx[mi][0], fmaxf(acc[mi][j][0], acc[mi][j][1]));
            mx[mi][1] = fmaxf(mx[mi][1], fmaxf(acc[mi][j][2], acc[mi][j][3]));
        }
#pragma unroll
        for (int h = 0; h < 2; h++) {
            float v = mx[mi][h];
            v = fmaxf(v, __shfl_xor_sync(0xffffffffu, v, 1));
            v = fmaxf(v, __shfl_xor_sync(0xffffffffu, v, 2));
            mx[mi][h] = v;
        }
    }

    float* smax = (float*)smem;
    __syncthreads();
    if (wn == 0 && (lane & 3) == 0) {
#pragma unroll
        for (int mi = 0; mi < 2; mi++) {
            int lr = wm * 32 + mi * 16 + (lane >> 2);
            smax[lr] = mx[mi][0]; smax[lr + 8] = mx[mi][1];
        }
    }
    __syncthreads();
    if (wn == 1 && (lane & 3) == 0) {
#pragma unroll
        for (int mi = 0; mi < 2; mi++) {
            int lr = wm * 32 + mi * 16 + (lane >> 2);
            smax[lr]     = fmaxf(smax[lr],     mx[mi][0]);
            smax[lr + 8] = fmaxf(smax[lr + 8], mx[mi][1]);
        }
    }
    __syncthreads();
    if (tid < 128) atomicMax(&g_rmax[b * NT + n0 + tid], fenc(smax[tid]));
}

// ============================================================================
// Kernel 3: energy + fused exp epilogue. Writes P'' fp16 + rowsum atomics.
// grid (32 m, 32 n, B), block 256
// ============================================================================
__global__ __launch_bounds__(256)
void energy_mma_kernel()
{
    extern __shared__ char smem[];
    const int b = blockIdx.z, m0 = blockIdx.x * 128, n0 = blockIdx.y * 128;
    const int tid = threadIdx.x;
    const int wid = tid >> 5, lane = tid & 31;
    const int wm = wid >> 1, wn = wid & 1;

    float acc[2][8][4];
#pragma unroll
    for (int mi = 0; mi < 2; mi++)
#pragma unroll
        for (int j = 0; j < 8; j++)
#pragma unroll
            for (int k = 0; k < 4; k++) acc[mi][j][k] = 0.f;

    gemm_mainloop<3, true>(smem, acc,
                  (const uint16_t*)(g_Qs + (size_t)(b * NT + n0) * 512), 512, 256,
                  (const uint16_t*)(g_Ks + (size_t)(b * NT + m0) * 512), 512, 256, 4);

    // fused softmax numerator: P'' = exp(S - rowmax) * 2^15, fp16 store
    const float SCALE = 32768.f;
    __half* Pb = g_Ph + (size_t)b * NT * NT;
    float rs[2][2] = {{0.f, 0.f}, {0.f, 0.f}};
#pragma unroll
    for (int mi = 0; mi < 2; mi++) {
        int r = n0 + wm * 32 + mi * 16 + (lane >> 2);
        float rm0 = fdec(g_rmax[b * NT + r]);
        float rm1 = fdec(g_rmax[b * NT + r + 8]);
#pragma unroll
        for (int j = 0; j < 8; j++) {
            float e0 = __expf(acc[mi][j][0] - rm0) * SCALE;
            float e1 = __expf(acc[mi][j][1] - rm0) * SCALE;
            float e2 = __expf(acc[mi][j][2] - rm1) * SCALE;
            float e3 = __expf(acc[mi][j][3] - rm1) * SCALE;
            rs[mi][0] += e0 + e1;
            rs[mi][1] += e2 + e3;
            int cm = m0 + wn * 64 + j * 8 + (lane & 3) * 2;
            *(__half2*)&Pb[(size_t)r * NT + cm]       = __floats2half2_rn(e0, e1);
            *(__half2*)&Pb[(size_t)(r + 8) * NT + cm] = __floats2half2_rn(e2, e3);
        }
#pragma unroll
        for (int h = 0; h < 2; h++) {
            float v = rs[mi][h];
            v += __shfl_xor_sync(0xffffffffu, v, 1);
            v += __shfl_xor_sync(0xffffffffu, v, 2);
            rs[mi][h] = v;
        }
    }

    float* ssum = (float*)smem;
    __syncthreads();
    if (wn == 0 && (lane & 3) == 0) {
#pragma unroll
        for (int mi = 0; mi < 2; mi++) {
            int lr = wm * 32 + mi * 16 + (lane >> 2);
            ssum[lr] = rs[mi][0]; ssum[lr + 8] = rs[mi][1];
        }
    }
    __syncthreads();
    if (wn == 1 && (lane & 3) == 0) {
#pragma unroll
        for (int mi = 0; mi < 2; mi++) {
            int lr = wm * 32 + mi * 16 + (lane >> 2);
            ssum[lr]     += rs[mi][0];
            ssum[lr + 8] += rs[mi][1];
        }
    }
    __syncthreads();
    if (tid < 128) atomicAdd(&g_sum[b * NT + n0 + tid], ssum[tid]);
}

// ============================================================================
// Kernel 4: out[b][o][n] = (sum_m P''[n][m] V[m][o]) / rowsum[n], fp16 mma.
// grid (2 o, 32 n, B), block 256
// ============================================================================
__global__ __launch_bounds__(256)
void av_mma_kernel(float* __restrict__ out)
{
    extern __shared__ char smem[];
    const int b = blockIdx.z, o0 = blockIdx.x * 128, n0 = blockIdx.y * 128;
    const int tid = threadIdx.x;
    const int wid = tid >> 5, lane = tid & 31;
    const int wm = wid >> 1, wn = wid & 1;

    float acc[2][8][4];
#pragma unroll
    for (int mi = 0; mi < 2; mi++)
#pragma unroll
        for (int j = 0; j < 8; j++)
#pragma unroll
            for (int k = 0; k < 4; k++) acc[mi][j][k] = 0.f;

    gemm_mainloop<1, false>(smem, acc,
                  (const uint16_t*)(g_Ph + (size_t)(b * NT + n0) * NT), NT, 0,
                  (const uint16_t*)(g_Vh + (size_t)(b * CC + o0) * NT), NT, 0, 64);

    // transpose C[n][o] -> out[b][o][n] via smem, with per-row normalization
    float* ts   = (float*)smem;                       // [128 n][132]
    float* sinv = (float*)(smem + 128 * 132 * 4);     // [128]
    __syncthreads();
    if (tid < 128) sinv[tid] = 1.f / g_sum[b * NT + n0 + tid];
#pragma unroll
    for (int mi = 0; mi < 2; mi++) {
        int r = wm * 32 + mi * 16 + (lane >> 2);
#pragma unroll
        for (int j = 0; j < 8; j++) {
            int o = wn * 64 + j * 8 + (lane & 3) * 2;
            *(float2*)&ts[(size_t)r * 132 + o]       = make_float2(acc[mi][j][0], acc[mi][j][1]);
            *(float2*)&ts[(size_t)(r + 8) * 132 + o] = make_float2(acc[mi][j][2], acc[mi][j][3]);
        }
    }
    __syncthreads();

    const int o = tid >> 1;
    const int nh = (tid & 1) * 64;
    float* dst = out + ((size_t)(b * CC + o0 + o)) * NT + n0 + nh;
#pragma unroll
    for (int g = 0; g < 16; g++) {
        int n = nh + g * 4;
        float4 v = make_float4(ts[(n + 0) * 132 + o] * sinv[n + 0],
                               ts[(n + 1) * 132 + o] * sinv[n + 1],
                               ts[(n + 2) * 132 + o] * sinv[n + 2],
                               ts[(n + 3) * 132 + o] * sinv[n + 3]);
        *(float4*)(dst + g * 4) = v;
    }
}

// ============================================================================
extern "C" void kernel_launch(void* const* d_in, const int* in_sizes, int n_in,
                              void* d_out, int out_size)
{
    const float* x  = (const float*)d_in[0];
    const float* Wq = (const float*)d_in[1];
    const float* bq = (const float*)d_in[2];
    const float* Wk = (const float*)d_in[3];
    const float* bk = (const float*)d_in[4];
    const float* Wv = (const float*)d_in[5];
    const float* bv = (const float*)d_in[6];
    float* out = (float*)d_out;

    cudaFuncSetAttribute(maxpass_kernel,
                         cudaFuncAttributeMaxDynamicSharedMemorySize, SM_TOTAL);
    cudaFuncSetAttribute(energy_mma_kernel,
                         cudaFuncAttributeMaxDynamicSharedMemorySize, SM_TOTAL);
    cudaFuncSetAttribute(av_mma_kernel,
                         cudaFuncAttributeMaxDynamicSharedMemorySize, SM_TOTAL);

    dim3 gproj(NT / 128, CC / 128, BB * 3);
    proj_kernel<<<gproj, 256>>>(x, Wq, bq, Wk, bk, Wv, bv);

    zero_kernel<<<(BB * NT + 255) / 256, 256>>>();

    dim3 gtile(NT / 128, NT / 128, BB);        // 32 x 32 x 4
    maxpass_kernel<<<gtile, 256, SM_TOTAL>>>();
    energy_mma_kernel<<<gtile, 256, SM_TOTAL>>>();

    dim3 gav(CC / 128, NT / 128, BB);          // 2 x 32 x 4
    av_mma_kernel<<<gav, 256, SM_TOTAL>>>(out);
}